// round 1
// baseline (speedup 1.0000x reference)
#include <cuda_runtime.h>

#define IMW 1024
#define IMH 1024
#define HW  (IMW * IMH)
#define TILE_W 16
#define TILE_H 32
#define HALO_W (TILE_W + 6)   // 22
#define HALO_H (TILE_H + 6)   // 38
#define SSTRIDE 24            // padded row stride (floats) -> disjoint banks for row pairs
#define CH_STRIDE (HALO_H * SSTRIDE)  // 912 floats per channel
#define EPSR 1e-4f

// ---- packed f32x2 helpers -------------------------------------------------
__device__ __forceinline__ unsigned long long pk2(float lo, float hi) {
    unsigned long long r;
    asm("mov.b64 %0, {%1, %2};" : "=l"(r) : "f"(lo), "f"(hi));
    return r;
}
__device__ __forceinline__ void ffma2(unsigned long long& d,
                                      unsigned long long a,
                                      unsigned long long b) {
    asm("fma.rn.f32x2 %0, %1, %2, %0;" : "+l"(d) : "l"(a), "l"(b));
}
__device__ __forceinline__ float upk(unsigned long long v, int hi) {
    float lo, h;
    asm("mov.b64 {%0, %1}, %2;" : "=f"(lo), "=f"(h) : "l"(v));
    return hi ? h : lo;
}

__global__ __launch_bounds__(256)
void ls_kernel(const float* __restrict__ inp,
               const float* __restrict__ depth,
               const float* __restrict__ alb,
               const float* __restrict__ nrm,
               float* __restrict__ out)
{
    // 11 channels: [valid(=1), depth, albedo x3, normal x3, input x3]
    __shared__ float S[11 * CH_STRIDE];

    const int tid = threadIdx.x;
    const int bx = blockIdx.x, by = blockIdx.y;
    const int gx0 = bx * TILE_W - 3;
    const int gy0 = by * TILE_H - 3;

    // ---- stage halo tile into smem (zeros outside the image) ----
    for (int idx = tid; idx < HALO_H * HALO_W; idx += 256) {
        const int r = idx / HALO_W;
        const int c = idx - r * HALO_W;
        const int gy = gy0 + r;
        const int gx = gx0 + c;
        float v[11];
        if ((unsigned)gy < (unsigned)IMH && (unsigned)gx < (unsigned)IMW) {
            const int g = gy * IMW + gx;
            v[0] = 1.0f;
            v[1] = depth[g];
            v[2] = alb[g];          v[3] = alb[g + HW];   v[4] = alb[g + 2 * HW];
            v[5] = nrm[g];          v[6] = nrm[g + HW];   v[7] = nrm[g + 2 * HW];
            v[8] = inp[g];          v[9] = inp[g + HW];   v[10] = inp[g + 2 * HW];
        } else {
#pragma unroll
            for (int ch = 0; ch < 11; ++ch) v[ch] = 0.0f;
        }
#pragma unroll
        for (int ch = 0; ch < 11; ++ch)
            S[ch * CH_STRIDE + r * SSTRIDE + c] = v[ch];
    }
    __syncthreads();

    // ---- per-thread: two vertically adjacent pixels, packed f32x2 ----
    const int tx = tid & 15;
    const int ty = tid >> 4;
    const int lx = tx;
    const int ly0 = ty * 2;

    unsigned long long ata[36];  // upper triangle i<=j of 8x8
    unsigned long long aty[24];  // i*3 + c
#pragma unroll
    for (int i = 0; i < 36; ++i) ata[i] = 0ULL;
#pragma unroll
    for (int i = 0; i < 24; ++i) aty[i] = 0ULL;

    const float* base = &S[ly0 * SSTRIDE + lx];
#pragma unroll 1
    for (int dy = 0; dy < 7; ++dy) {
        const float* rp = base + dy * SSTRIDE;
#pragma unroll
        for (int dx = 0; dx < 7; ++dx) {
            unsigned long long v[11];
#pragma unroll
            for (int ch = 0; ch < 11; ++ch) {
                const float a = rp[ch * CH_STRIDE + dx];            // pixel0 tap
                const float b = rp[ch * CH_STRIDE + dx + SSTRIDE];  // pixel1 tap
                v[ch] = pk2(a, b);
            }
            int k = 0;
#pragma unroll
            for (int i = 0; i < 8; ++i)
#pragma unroll
                for (int j = i; j < 8; ++j) { ffma2(ata[k], v[i], v[j]); ++k; }
#pragma unroll
            for (int i = 0; i < 8; ++i)
#pragma unroll
                for (int c = 0; c < 3; ++c) ffma2(aty[i * 3 + c], v[i], v[8 + c]);
        }
    }

    // ---- per-pixel solve:  x = (AtA + eps I)^{-1} f_center ;  out_c = x . AtY_c
#pragma unroll 1
    for (int p = 0; p < 2; ++p) {
        float A[8][9];
        {
            int k = 0;
#pragma unroll
            for (int i = 0; i < 8; ++i)
#pragma unroll
                for (int j = i; j < 8; ++j) {
                    const float vv = upk(ata[k], p); ++k;
                    A[i][j] = vv;
                    A[j][i] = vv;
                }
        }
#pragma unroll
        for (int i = 0; i < 8; ++i) A[i][i] += EPSR;

        // RHS: center-pixel features
        const float* cp = &S[(ly0 + 3 + p) * SSTRIDE + (lx + 3)];
#pragma unroll
        for (int i = 0; i < 8; ++i) A[i][8] = cp[i * CH_STRIDE];

        // Gaussian elimination (no pivoting; SPD + Tikhonov)
#pragma unroll
        for (int kk = 0; kk < 8; ++kk) {
            const float inv = 1.0f / A[kk][kk];
#pragma unroll
            for (int j = 0; j < 9; ++j)
                if (j > kk) A[kk][j] *= inv;
#pragma unroll
            for (int r = 0; r < 8; ++r)
                if (r > kk) {
                    const float m = A[r][kk];
#pragma unroll
                    for (int j = 0; j < 9; ++j)
                        if (j > kk) A[r][j] = fmaf(-m, A[kk][j], A[r][j]);
                }
        }
        float x[8];
#pragma unroll
        for (int i = 7; i >= 0; --i) {
            float s = A[i][8];
#pragma unroll
            for (int j = 0; j < 8; ++j)
                if (j > i) s = fmaf(-A[i][j], x[j], s);
            x[i] = s;
        }

        const int gy = by * TILE_H + ly0 + p;
        const int gx = bx * TILE_W + lx;
#pragma unroll
        for (int c = 0; c < 3; ++c) {
            float o = 0.0f;
#pragma unroll
            for (int i = 0; i < 8; ++i)
                o = fmaf(x[i], upk(aty[i * 3 + c], p), o);
            out[c * HW + gy * IMW + gx] = o;
        }
    }
}

extern "C" void kernel_launch(void* const* d_in, const int* in_sizes, int n_in,
                              void* d_out, int out_size) {
    const float* inp   = (const float*)d_in[0];
    const float* depth = (const float*)d_in[1];
    const float* alb   = (const float*)d_in[2];
    const float* nrm   = (const float*)d_in[3];
    float* out = (float*)d_out;

    dim3 grid(IMW / TILE_W, IMH / TILE_H);
    ls_kernel<<<grid, 256>>>(inp, depth, alb, nrm, out);
}